// round 2
// baseline (speedup 1.0000x reference)
#include <cuda_runtime.h>
#include <cuda_bf16.h>

#define EPS_F 1e-7f

// Per-channel coefficient tables (C = 1024 channels).
// cA[c] = {b0, b1, b2, g}  with b_i = g * mag * n_i
// cR[c] = 1 / (g + 1)
__device__ float4 g_cA[1024];
__device__ float  g_cR[1024];

__global__ void lorentz_coef_kernel(const float* __restrict__ Bo) {
    int c = blockIdx.x * blockDim.x + threadIdx.x;
    if (c >= 1024) return;
    float b0 = Bo[3 * c + 0];
    float b1 = Bo[3 * c + 1];
    float b2 = Bo[3 * c + 2];
    float m2 = b0 * b0 + b1 * b1 + b2 * b2;
    float mag = sqrtf(m2);
    mag = fminf(fmaxf(mag, EPS_F), 1.0f - EPS_F);
    // n = Bo / mag (with clipped mag), g = 1/sqrt(1 - mag^2)
    float inv_mag = 1.0f / mag;
    float n0 = b0 * inv_mag, n1 = b1 * inv_mag, n2 = b2 * inv_mag;
    float g = rsqrtf(1.0f - mag * mag);
    float gm = g * mag;
    float4 A;
    A.x = gm * n0;
    A.y = gm * n1;
    A.z = gm * n2;
    A.w = g;
    g_cA[c] = A;
    g_cR[c] = 1.0f / (g + 1.0f);
}

// Each thread processes ELEMS elements of the SAME channel (stride = NTHREADS
// float4s, a multiple of 1024), so the coefficient load amortizes and the 4
// global float4 loads are independent (MLP=4).
__global__ __launch_bounds__(256) void lorentz_apply_kernel(
    const float4* __restrict__ T4, float4* __restrict__ out4)
{
    const unsigned tid = blockIdx.x * 256u + threadIdx.x;   // 0 .. 2^21-1
    const int c = tid & 1023;

    const float4 A = g_cA[c];
    const float  r = g_cR[c];

    const unsigned STRIDE = 1u << 21;  // 2,097,152 float4s

    float4 x0 = T4[tid + 0u * STRIDE];
    float4 x1 = T4[tid + 1u * STRIDE];
    float4 x2 = T4[tid + 2u * STRIDE];
    float4 x3 = T4[tid + 3u * STRIDE];

    float4 o0, o1, o2, o3;

    {
        float dot = fmaf(A.x, x0.y, fmaf(A.y, x0.z, A.z * x0.w));
        float k   = fmaf(r, dot, -x0.x);           // r*dot - t
        o0.x = fmaf(A.w, x0.x, -dot);              // g*t - dot
        o0.y = fmaf(A.x, k, x0.y);
        o0.z = fmaf(A.y, k, x0.z);
        o0.w = fmaf(A.z, k, x0.w);
    }
    {
        float dot = fmaf(A.x, x1.y, fmaf(A.y, x1.z, A.z * x1.w));
        float k   = fmaf(r, dot, -x1.x);
        o1.x = fmaf(A.w, x1.x, -dot);
        o1.y = fmaf(A.x, k, x1.y);
        o1.z = fmaf(A.y, k, x1.z);
        o1.w = fmaf(A.z, k, x1.w);
    }
    {
        float dot = fmaf(A.x, x2.y, fmaf(A.y, x2.z, A.z * x2.w));
        float k   = fmaf(r, dot, -x2.x);
        o2.x = fmaf(A.w, x2.x, -dot);
        o2.y = fmaf(A.x, k, x2.y);
        o2.z = fmaf(A.y, k, x2.z);
        o2.w = fmaf(A.z, k, x2.w);
    }
    {
        float dot = fmaf(A.x, x3.y, fmaf(A.y, x3.z, A.z * x3.w));
        float k   = fmaf(r, dot, -x3.x);
        o3.x = fmaf(A.w, x3.x, -dot);
        o3.y = fmaf(A.x, k, x3.y);
        o3.z = fmaf(A.y, k, x3.z);
        o3.w = fmaf(A.z, k, x3.w);
    }

    out4[tid + 0u * STRIDE] = o0;
    out4[tid + 1u * STRIDE] = o1;
    out4[tid + 2u * STRIDE] = o2;
    out4[tid + 3u * STRIDE] = o3;
}

extern "C" void kernel_launch(void* const* d_in, const int* in_sizes, int n_in,
                              void* d_out, int out_size) {
    const float* T  = (const float*)d_in[0];   // 8192*1024*4 fp32
    const float* Bo = (const float*)d_in[1];   // 1024*3 fp32
    float* out = (float*)d_out;

    lorentz_coef_kernel<<<4, 256>>>(Bo);

    // 8192*1024 = 2^23 four-vectors; 4 per thread -> 2^21 threads -> 8192 blocks
    lorentz_apply_kernel<<<8192, 256>>>((const float4*)T, (float4*)out);
}

// round 7
// speedup vs baseline: 1.0927x; 1.0927x over previous
#include <cuda_runtime.h>
#include <cuda_bf16.h>

#define EPS_F 1e-7f

// Single fused kernel: each thread derives its channel's boost coefficients
// (2x rsqrt + a few FMAs, fully hidden under DRAM latency), then streams
// 4 four-vectors of that channel (stride = 2^21 float4s, a multiple of 1024,
// so all 4 elements share the channel and the 4 LDG.128 are independent).
// Streaming cache hints (.cs) on the 256MB T/out traffic keep the 126MB L2
// from thrashing on data with zero reuse; Bo (12KB, reused 2048x) stays cached.
__global__ __launch_bounds__(256) void lorentz_fused_kernel(
    const float4* __restrict__ T4,
    const float*  __restrict__ Bo,
    float4* __restrict__ out4)
{
    const unsigned tid = blockIdx.x * 256u + threadIdx.x;   // 0 .. 2^21-1
    const int c = tid & 1023;

    // ---- per-channel coefficients (redundant per thread; ~1us chip-wide) ----
    const float b0 = __ldg(&Bo[3 * c + 0]);
    const float b1 = __ldg(&Bo[3 * c + 1]);
    const float b2 = __ldg(&Bo[3 * c + 2]);
    const float m2 = fmaf(b0, b0, fmaf(b1, b1, b2 * b2));

    float n0, n1, n2, g;
    const float mag  = sqrtf(m2);
    const float magc = fminf(fmaxf(mag, EPS_F), 1.0f - EPS_F);
    if (magc == mag) {
        // fast path (always taken for this data): no clipping active
        const float inv = rsqrtf(m2);
        n0 = b0 * inv; n1 = b1 * inv; n2 = b2 * inv;
        g  = rsqrtf(1.0f - m2);
    } else {
        // exact reference semantics when mag is clipped (rare/never)
        n0 = b0 / magc; n1 = b1 / magc; n2 = b2 / magc;
        g  = rsqrtf(1.0f - magc * magc);
    }
    const float gb  = g * magc;   // g * mag
    const float gm1 = g - 1.0f;

    // ---- stream 4 elements ----
    const unsigned STRIDE = 1u << 21;  // 2,097,152 float4s

    float4 x0 = __ldcs(&T4[tid + 0u * STRIDE]);
    float4 x1 = __ldcs(&T4[tid + 1u * STRIDE]);
    float4 x2 = __ldcs(&T4[tid + 2u * STRIDE]);
    float4 x3 = __ldcs(&T4[tid + 3u * STRIDE]);

    float4 o0, o1, o2, o3;

    {
        float dot = fmaf(n0, x0.y, fmaf(n1, x0.z, n2 * x0.w));
        float k   = fmaf(gm1, dot, -(gb * x0.x));   // (g-1)(n.v) - g*mag*t
        o0.x = fmaf(g, x0.x, -(gb * dot));          // g*t - g*mag*(n.v)
        o0.y = fmaf(n0, k, x0.y);
        o0.z = fmaf(n1, k, x0.z);
        o0.w = fmaf(n2, k, x0.w);
    }
    {
        float dot = fmaf(n0, x1.y, fmaf(n1, x1.z, n2 * x1.w));
        float k   = fmaf(gm1, dot, -(gb * x1.x));
        o1.x = fmaf(g, x1.x, -(gb * dot));
        o1.y = fmaf(n0, k, x1.y);
        o1.z = fmaf(n1, k, x1.z);
        o1.w = fmaf(n2, k, x1.w);
    }
    {
        float dot = fmaf(n0, x2.y, fmaf(n1, x2.z, n2 * x2.w));
        float k   = fmaf(gm1, dot, -(gb * x2.x));
        o2.x = fmaf(g, x2.x, -(gb * dot));
        o2.y = fmaf(n0, k, x2.y);
        o2.z = fmaf(n1, k, x2.z);
        o2.w = fmaf(n2, k, x2.w);
    }
    {
        float dot = fmaf(n0, x3.y, fmaf(n1, x3.z, n2 * x3.w));
        float k   = fmaf(gm1, dot, -(gb * x3.x));
        o3.x = fmaf(g, x3.x, -(gb * dot));
        o3.y = fmaf(n0, k, x3.y);
        o3.z = fmaf(n1, k, x3.z);
        o3.w = fmaf(n2, k, x3.w);
    }

    __stcs(&out4[tid + 0u * STRIDE], o0);
    __stcs(&out4[tid + 1u * STRIDE], o1);
    __stcs(&out4[tid + 2u * STRIDE], o2);
    __stcs(&out4[tid + 3u * STRIDE], o3);
}

extern "C" void kernel_launch(void* const* d_in, const int* in_sizes, int n_in,
                              void* d_out, int out_size) {
    const float* T  = (const float*)d_in[0];   // 8192*1024*4 fp32
    const float* Bo = (const float*)d_in[1];   // 1024*3 fp32
    float* out = (float*)d_out;

    // 8192*1024 = 2^23 four-vectors; 4 per thread -> 2^21 threads -> 8192 blocks
    lorentz_fused_kernel<<<8192, 256>>>((const float4*)T, Bo, (float4*)out);
}